// round 16
// baseline (speedup 1.0000x reference)
#include <cuda_runtime.h>
#include <cstdint>

#define Bn    8
#define Nn    8192
#define Cn    91
#define CAPc  163840          // >= max kept candidates per image
#define NB    9216            // histogram bins over score float bits >> 12
#define BASE_BIN 251084       // bits(0.05f) >> 12
#define SEL_CAP 1024
#define TPB   1024
#define DETS  100
#define CLIPV 4.135166556742356f   // log(1000/16)
#define FULLM 0xffffffffu

// ------------------------------------------------------------------
// static device scratch (zero-initialized at load; k_nms restores the
// zeros it consumed -> graph-replay deterministic)
// ------------------------------------------------------------------
__device__ unsigned long long g_keys[Bn][CAPc];
__device__ int                g_cnt [Bn];
__device__ int                g_hist[Bn][NB];

__device__ __forceinline__ void stf(float* o, int i, float v, int n) {
    if (i < n) o[i] = v;
}

// reference-rounding IoU on offset coordinates; returns (iou > 0.5)
__device__ __forceinline__ bool iou_sup(float4 A, float4 Bx, float off) {
    float ax1 = A.x + off, ay1 = A.y + off, ax2 = A.z + off, ay2 = A.w + off;
    float bx1 = Bx.x + off, by1 = Bx.y + off, bx2 = Bx.z + off, by2 = Bx.w + off;
    float ltx = fmaxf(ax1, bx1), lty = fmaxf(ay1, by1);
    float rbx = fminf(ax2, bx2), rby = fminf(ay2, by2);
    float ww = fmaxf(rbx - ltx, 0.f), hh = fmaxf(rby - lty, 0.f);
    float inter = ww * hh;
    float a1 = (ax2 - ax1) * (ay2 - ay1);
    float a2 = (bx2 - bx1) * (by2 - by1);
    float iou = __fdiv_rn(inter, a1 + a2 - inter + 1e-9f);
    return iou > 0.5f;
}

// byte-identical box decode for candidate (g, c)
__device__ __forceinline__ float4 decode_box(const float* __restrict__ reg,
                                             const float* __restrict__ props,
                                             int g, int c) {
    float4 p = reinterpret_cast<const float4*>(props)[g];
    float w  = p.z - p.x;
    float h  = p.w - p.y;
    float cx = p.x + 0.5f * w;
    float cy = p.y + 0.5f * h;
    const float4* Q = reinterpret_cast<const float4*>(reg + (size_t)g * (Cn * 4));
    float4 q = Q[c];
    float dx = __fdiv_rn(q.x, 10.0f);
    float dy = __fdiv_rn(q.y, 10.0f);
    float dw = fminf(__fdiv_rn(q.z, 5.0f), CLIPV);
    float dh = fminf(__fdiv_rn(q.w, 5.0f), CLIPV);
    float pcx = dx * w + cx;
    float pcy = dy * h + cy;
    float pw  = expf(dw) * w;
    float ph  = expf(dh) * h;
    float x1 = fminf(fmaxf(pcx - 0.5f * pw, 0.f), 800.f);
    float y1 = fminf(fmaxf(pcy - 0.5f * ph, 0.f), 800.f);
    float x2 = fminf(fmaxf(pcx + 0.5f * pw, 0.f), 800.f);
    float y2 = fminf(fmaxf(pcy + 0.5f * ph, 0.f), 800.f);
    return make_float4(x1, y1, x2, y2);
}

// decode + filter + key emit for one proposal's survivors (warp-wide)
__device__ __forceinline__ void emit_prop(int g, int lane,
                                          unsigned mA, unsigned mB, unsigned mC,
                                          float e0, float e1, float e2, float s,
                                          const float* __restrict__ reg,
                                          const float* __restrict__ props,
                                          bool& ok, float& sc, int& c) {
    int c0  = __popc(mA);
    int c01 = c0 + __popc(mB);
    int tot = c01 + __popc(mC);
    ok = false; sc = 0.f; c = 0;
    if (tot == 0) return;

    int src = 0, k = 0;
    if (lane < c0)       { k = 0; src = __fns(mA, 0, lane + 1); }
    else if (lane < c01) { k = 1; src = __fns(mB, 0, lane - c0 + 1); }
    else if (lane < tot) { k = 2; src = __fns(mC, 0, lane - c01 + 1); }
    src &= 31;
    float eA = __shfl_sync(FULLM, e0, src);
    float eB = __shfl_sync(FULLM, e1, src);
    float eC = __shfl_sync(FULLM, e2, src);
    float e  = (k == 2) ? eC : ((k == 1) ? eB : eA);
    c = src + (k << 5);

    ok = (lane < tot);
    sc = __fdiv_rn(e, s);                 // exact softmax value
    ok = ok && (sc > 0.05f);
    if (ok) {
        float4 bx = decode_box(reg, props, g, c);
        ok = ((bx.z - bx.x) >= 1.0f) && ((bx.w - bx.y) >= 1.0f);
    }
}

// ------------------------------------------------------------------
// K1: four proposals per warp, interleaved chains + histogram
// ------------------------------------------------------------------
__global__ __launch_bounds__(256) void k_cand(const float* __restrict__ logits,
                                              const float* __restrict__ reg,
                                              const float* __restrict__ props) {
    int warp = threadIdx.x >> 5;
    int lane = threadIdx.x & 31;
    int g0 = blockIdx.x * 32 + warp * 4;      // 4 proposals, same image
    int b  = g0 >> 13;

    float l0[4], l1[4], l2[4], mx[4];
    #pragma unroll
    for (int p = 0; p < 4; p++) {
        const float* L = logits + (size_t)(g0 + p) * Cn;
        l0[p] = L[lane];
        l1[p] = (lane + 32 < Cn) ? L[lane + 32] : -1e30f;
        l2[p] = (lane + 64 < Cn) ? L[lane + 64] : -1e30f;
    }
    #pragma unroll
    for (int p = 0; p < 4; p++) mx[p] = fmaxf(l0[p], fmaxf(l1[p], l2[p]));
    #pragma unroll
    for (int o = 16; o; o >>= 1) {
        #pragma unroll
        for (int p = 0; p < 4; p++)
            mx[p] = fmaxf(mx[p], __shfl_xor_sync(FULLM, mx[p], o));
    }

    float e0[4], e1[4], e2[4], sden[4];
    #pragma unroll
    for (int p = 0; p < 4; p++) {
        e0[p] = expf(l0[p] - mx[p]);
        e1[p] = (lane + 32 < Cn) ? expf(l1[p] - mx[p]) : 0.0f;
        e2[p] = (lane + 64 < Cn) ? expf(l2[p] - mx[p]) : 0.0f;
        sden[p] = e0[p] + e1[p] + e2[p];
    }
    #pragma unroll
    for (int o = 16; o; o >>= 1) {
        #pragma unroll
        for (int p = 0; p < 4; p++)
            sden[p] += __shfl_xor_sync(FULLM, sden[p], o);
    }

    unsigned mA[4], mB[4], mC[4];
    unsigned anym = 0;
    #pragma unroll
    for (int p = 0; p < 4; p++) {
        float pt = 0.0497f * sden[p];   // conservative prefilter (>> 1ulp margin)
        mA[p] = __ballot_sync(FULLM, (lane >= 1) && (e0[p] > pt));
        mB[p] = __ballot_sync(FULLM, e1[p] > pt);
        mC[p] = __ballot_sync(FULLM, e2[p] > pt);
        anym |= mA[p] | mB[p] | mC[p];
    }
    if (anym == 0u) return;                   // warp-uniform

    bool ok[4]; float sc[4]; int cc[4];
    #pragma unroll
    for (int p = 0; p < 4; p++)
        emit_prop(g0 + p, lane, mA[p], mB[p], mC[p],
                  e0[p], e1[p], e2[p], sden[p], reg, props,
                  ok[p], sc[p], cc[p]);

    unsigned fm[4]; int pc[4];
    int tot = 0;
    #pragma unroll
    for (int p = 0; p < 4; p++) {
        fm[p] = __ballot_sync(FULLM, ok[p]);
        pc[p] = __popc(fm[p]);
        tot += pc[p];
    }
    if (tot) {
        int base = 0;
        if (lane == 0) base = atomicAdd(&g_cnt[b], tot);
        base = __shfl_sync(FULLM, base, 0);
        unsigned below = (1u << lane) - 1u;
        int off = base;
        #pragma unroll
        for (int p = 0; p < 4; p++) {
            if (ok[p]) {
                int pos = off + __popc(fm[p] & below);
                if (pos < CAPc) {
                    int n = (g0 + p) & (Nn - 1);
                    unsigned m = (unsigned)(n * 90 + (cc[p] - 1));
                    unsigned sbb = __float_as_uint(sc[p]);
                    g_keys[b][pos] = ((unsigned long long)sbb << 32) | (0xFFFFFFFFu - m);
                    int bin = (int)(sbb >> 12) - BASE_BIN;
                    bin = max(0, min(bin, NB - 1));
                    atomicAdd(&g_hist[b][bin], 1);
                }
            }
            off += pc[p];
        }
    }
}

// ------------------------------------------------------------------
// K2 shared memory
// ------------------------------------------------------------------
struct SM {
    float4 sbox[SEL_CAP];               // window boxes (scan order)
    float4 cls_acc[32][DETS];           // fallback-path accepted scratch
    float4 abox[DETS];                  // global accepted boxes
    unsigned long long skey[SEL_CAP];
    unsigned long long svkey[SEL_CAP];  // compacted survivor keys
    unsigned mask[SEL_CAP][4];          // per-rank suppression bitmask (<=128)
    int    slbl[SEL_CAP];
    int    sfx[NB];
    int    chunkcnt[32][128];           // per-(chunk,warp) class counts / bases
    int    cls_rank[SEL_CAP];           // within-class SCORE rank
    int    cls_list[SEL_CAP];           // unordered class lists
    int    cls_srt[SEL_CAP];            // score-sorted class lists
    int    sflag[SEL_CAP];
    int    presup[SEL_CAP];
    int    svidx[SEL_CAP];              // survivor -> window index
    int    cls_cnt[128];
    int    cls_off[96];
    int    albl[DETS];
    int    wtot[32], wexc[32], wsum[32];
    int    s_cnt, s_acc, s_surv;
};

__global__ __launch_bounds__(TPB) void k_nms(const float* __restrict__ reg,
                                             const float* __restrict__ props,
                                             float* __restrict__ out, int out_size) {
    extern __shared__ __align__(16) char smraw[];
    SM* sm = reinterpret_cast<SM*>(smraw);
    int b = blockIdx.x;
    int t = threadIdx.x;
    int lane = t & 31;
    int warp = t >> 5;

    int Ktot = min(g_cnt[b], CAPc);

    // ---- load histogram (built by k_cand) + restore zeros ----
    const int PER = NB / TPB;   // 9
    int lo = t * PER;
    int cnts[PER];
    #pragma unroll
    for (int i = 0; i < PER; i++) {
        cnts[i] = g_hist[b][lo + i];
        g_hist[b][lo + i] = 0;
    }

    // ---- hierarchical suffix sums ----
    int ls = 0;
    #pragma unroll
    for (int i = 0; i < PER; i++) ls += cnts[i];
    int v = ls;
    #pragma unroll
    for (int off = 1; off < 32; off <<= 1) {
        int u = __shfl_down_sync(FULLM, v, off);
        if (lane + off < 32) v += u;
    }
    if (lane == 0) sm->wtot[warp] = v;
    __syncthreads();
    if (t < 32) {
        int x = sm->wtot[t];
        int vv = x;
        #pragma unroll
        for (int off = 1; off < 32; off <<= 1) {
            int u = __shfl_down_sync(FULLM, vv, off);
            if (t + off < 32) vv += u;
        }
        sm->wexc[t] = vv - x;
    }
    if (t == 0) sm->s_acc = 0;
    __syncthreads();
    int run = sm->wexc[warp] + (v - ls);
    for (int i = PER - 1; i >= 0; i--) {
        run += cnts[i];
        sm->sfx[lo + i] = run;
    }
    __syncthreads();

    int b_hi = NB;

    while (sm->s_acc < DETS) {
        int top = (b_hi < NB) ? sm->sfx[b_hi] : 0;
        if (b_hi == 0 || sm->sfx[0] - top == 0) break;

        // smallest wlo with sfx[wlo] - top <= SEL_CAP
        int sl = 0, sh = b_hi;
        while (sl < sh) {
            int mid = (sl + sh) >> 1;
            if (sm->sfx[mid] - top <= SEL_CAP) sh = mid; else sl = mid + 1;
        }
        int wlo = sl;
        if (wlo >= b_hi) wlo = b_hi - 1;
        int whi = b_hi;
        b_hi = wlo;

        if (t == 0) sm->s_cnt = 0;
        __syncthreads();
        // ---- MLP-8 selection scan ----
        for (int i0 = 0; i0 < Ktot; i0 += TPB * 8) {
            unsigned long long kv[8];
            #pragma unroll
            for (int k = 0; k < 8; k++) {
                int i = i0 + k * TPB + t;
                kv[k] = (i < Ktot) ? g_keys[b][i] : 0ULL;
            }
            #pragma unroll
            for (int k = 0; k < 8; k++) {
                if (kv[k]) {
                    int bin = (int)((unsigned)(kv[k] >> 32) >> 12) - BASE_BIN;
                    bin = max(0, min(bin, NB - 1));
                    if (bin >= wlo && bin < whi) {
                        int pos = atomicAdd(&sm->s_cnt, 1);
                        if (pos < SEL_CAP) sm->skey[pos] = kv[k];
                    }
                }
            }
        }
        __syncthreads();
        int nsel = min(sm->s_cnt, SEL_CAP);
        if (nsel == 0) continue;

        // ---- decode boxes + labels (scan order); reset counters ----
        int mylbl;
        unsigned long long mykey = 0ULL;
        if (t < nsel) {
            mykey = sm->skey[t];
            unsigned m = 0xFFFFFFFFu - (unsigned)mykey;
            int n = (int)(m / 90u);
            int c = (int)(m % 90u) + 1;
            sm->sbox[t] = decode_box(reg, props, b * Nn + n, c);
            sm->slbl[t] = c;
            mylbl = c;
        } else {
            mylbl = 96 + lane;            // unique-per-lane pad label
        }
        sm->sflag[t] = 0;
        {
            #pragma unroll
            for (int i = 0; i < 4; i++) sm->chunkcnt[(t * 4 + i) >> 7][(t * 4 + i) & 127] = 0;
        }
        __syncthreads();

        // ---- parallel per-chunk ranks: warp w handles items w*32+lane ----
        unsigned peers = __match_any_sync(FULLM, mylbl);
        int lrank = __popc(peers & ((1u << lane) - 1u));
        int leader = __ffs(peers) - 1;
        if (lane == leader) sm->chunkcnt[warp][mylbl] = __popc(peers);
        __syncthreads();

        // ---- per-class prefix across the 32 chunks (128 threads) ----
        if (t < 128) {
            int run2 = 0;
            #pragma unroll 1
            for (int w = 0; w < 32; w++) {
                int tmp = sm->chunkcnt[w][t];
                sm->chunkcnt[w][t] = run2;   // becomes chunk base
                run2 += tmp;
            }
            sm->cls_cnt[t] = run2;
        }
        __syncthreads();

        // ---- exclusive offsets over classes 0..95 ----
        if (t < 32) {
            int c0i = t * 3;
            int s0 = sm->cls_cnt[c0i], s1 = sm->cls_cnt[c0i + 1], s2 = sm->cls_cnt[c0i + 2];
            int tt = s0 + s1 + s2;
            int rn = tt;
            #pragma unroll
            for (int off = 1; off < 32; off <<= 1) {
                int u = __shfl_up_sync(FULLM, rn, off);
                if (lane >= off) rn += u;
            }
            int ex = rn - tt;
            sm->cls_off[c0i] = ex;
            sm->cls_off[c0i + 1] = ex + s0;
            sm->cls_off[c0i + 2] = ex + s0 + s1;
        }
        __syncthreads();

        // ---- scatter unordered class lists ----
        if (t < nsel)
            sm->cls_list[sm->cls_off[mylbl] + sm->chunkcnt[warp][mylbl] + lrank] = t;
        int acc0 = sm->s_acc;
        int quota = DETS - acc0;
        __syncthreads();

        // ---- counting rank within class (keys unique -> permutation) ----
        if (t < nsel) {
            int off = sm->cls_off[mylbl];
            int cnt = sm->cls_cnt[mylbl];
            int sr = 0;
            for (int j = 0; j < cnt; j++) {
                int widx = sm->cls_list[off + j];
                sr += (sm->skey[widx] > mykey) ? 1 : 0;
            }
            sm->cls_rank[t] = sr;
            sm->cls_srt[off + sr] = t;       // score-sorted class list
        }

        // ---- phase A: presuppression by prior-round accepted boxes ----
        {
            int ps = 0;
            if (t < nsel && acc0 > 0) {
                float4 bi = sm->sbox[t];
                int li = mylbl;
                float offv = (float)li * 801.0f;
                for (int a = 0; a < acc0; a++) {
                    if (sm->albl[a] == li && iou_sup(sm->abox[a], bi, offv)) { ps = 1; break; }
                }
            }
            sm->presup[t] = ps;
        }
        __syncthreads();

        // ---- phase B: parallel mask build (classes with cnt <= 128) ----
        if (t < nsel) {
            int c = mylbl;
            int cnt = sm->cls_cnt[c];
            if (cnt <= 128) {
                int off = sm->cls_off[c];
                int r = sm->cls_rank[t];
                float4 bi = sm->sbox[t];
                float offv = (float)c * 801.0f;
                unsigned w0 = 0, w1 = 0, w2 = 0, w3 = 0;
                for (int j = r + 1; j < cnt; j++) {
                    int widx = sm->cls_srt[off + j];
                    if (iou_sup(bi, sm->sbox[widx], offv)) {
                        int wsel = j >> 5;
                        unsigned bit = 1u << (j & 31);
                        if      (wsel == 0) w0 |= bit;
                        else if (wsel == 1) w1 |= bit;
                        else if (wsel == 2) w2 |= bit;
                        else                w3 |= bit;
                    }
                }
                sm->mask[off + r][0] = w0;
                sm->mask[off + r][1] = w1;
                sm->mask[off + r][2] = w2;
                sm->mask[off + r][3] = w3;
            }
        }
        __syncthreads();

        // ---- phase C: 90 concurrent single-lane greedy word-walks ----
        if (t < 90) {
            int c = t + 1;
            int cnt = sm->cls_cnt[c];
            if (cnt > 0 && cnt <= 128) {
                int off = sm->cls_off[c];
                unsigned S0 = 0, S1 = 0, S2 = 0, S3 = 0;
                int newacc = 0;
                for (int j = 0; j < cnt; j++) {
                    int wsel = j >> 5;
                    unsigned bit = 1u << (j & 31);
                    unsigned Sw = (wsel == 0) ? S0 : (wsel == 1) ? S1 : (wsel == 2) ? S2 : S3;
                    int widx = sm->cls_srt[off + j];
                    if (!(Sw & bit) && !sm->presup[widx]) {
                        sm->sflag[widx] = 1;
                        newacc++;
                        if (newacc >= quota) break;
                        S0 |= sm->mask[off + j][0];
                        S1 |= sm->mask[off + j][1];
                        S2 |= sm->mask[off + j][2];
                        S3 |= sm->mask[off + j][3];
                    }
                }
            }
        }

        // ---- fallback: classes with cnt > 128 use serial warp greedy ----
        #pragma unroll
        for (int jc = 0; jc < 3; jc++) {
            int c = warp + 1 + 32 * jc;
            if (c > 90) continue;
            int cnt = sm->cls_cnt[c];
            if (cnt <= 128) continue;       // handled by mask path
            int off = sm->cls_off[c];
            float offv = (float)c * 801.0f;

            int nacc = 0;
            for (int a0 = 0; a0 < acc0; a0 += 32) {
                int a = a0 + lane;
                bool mth = (a < acc0) && (sm->albl[a] == c);
                unsigned mm = __ballot_sync(FULLM, mth);
                if (mth) sm->cls_acc[warp][nacc + __popc(mm & ((1u << lane) - 1u))] = sm->abox[a];
                nacc += __popc(mm);
            }

            int newacc = 0;
            for (int j = 0; j < cnt; j++) {
                int i = sm->cls_srt[off + j];
                float4 bx = sm->sbox[i];
                bool sup = false;
                for (int a = lane; a < nacc; a += 32)
                    sup |= iou_sup(sm->cls_acc[warp][a], bx, offv);
                if (!__any_sync(FULLM, sup)) {
                    if (lane == 0) {
                        sm->sflag[i] = 1;
                        sm->cls_acc[warp][nacc] = bx;
                    }
                    nacc++;
                    newacc++;
                    if (newacc >= quota) break;
                }
            }
        }
        __syncthreads();

        // ---- compact survivors (arbitrary order) ----
        {
            int f = sm->sflag[t];
            int scn = f;
            #pragma unroll
            for (int off = 1; off < 32; off <<= 1) {
                int u = __shfl_up_sync(FULLM, scn, off);
                if (lane >= off) scn += u;
            }
            if (lane == 31) sm->wsum[warp] = scn;
            __syncthreads();
            if (t < 32) {
                int x = sm->wsum[t];
                int s2 = x;
                #pragma unroll
                for (int off = 1; off < 32; off <<= 1) {
                    int u = __shfl_up_sync(FULLM, s2, off);
                    if (t >= off) s2 += u;
                }
                sm->wsum[t] = s2 - x;
            }
            __syncthreads();
            int incl = scn + sm->wsum[warp];
            int r = incl - f;
            if (f) {
                sm->svkey[r] = mykey;
                sm->svidx[r] = t;
            }
            if (t == TPB - 1) sm->s_surv = incl;
            __syncthreads();
        }

        int scnt = sm->s_surv;
        if (scnt == 0) continue;
        int stored = min(scnt, quota);

        // ---- counting rank among survivors; output rank < quota ----
        if (t < scnt) {
            unsigned long long k = sm->svkey[t];
            int rr = 0;
            for (int j = 0; j < scnt; j++)
                rr += (sm->svkey[j] > k) ? 1 : 0;
            if (rr < quota) {
                int wi = sm->svidx[t];
                float4 bx = sm->sbox[wi];
                int lbl = sm->slbl[wi];
                int slot = acc0 + rr;
                sm->abox[slot] = bx;
                sm->albl[slot] = lbl;
                float sc = __uint_as_float((unsigned)(k >> 32));
                stf(out, b * (DETS * 4) + slot * 4 + 0, bx.x, out_size);
                stf(out, b * (DETS * 4) + slot * 4 + 1, bx.y, out_size);
                stf(out, b * (DETS * 4) + slot * 4 + 2, bx.z, out_size);
                stf(out, b * (DETS * 4) + slot * 4 + 3, bx.w, out_size);
                stf(out, Bn * DETS * 4 + b * DETS + slot, sc, out_size);
                stf(out, Bn * DETS * 5 + b * DETS + slot, (float)lbl, out_size);
                stf(out, Bn * DETS * 6 + b * DETS + slot, 1.0f, out_size);
            }
        }
        __syncthreads();
        if (t == 0) sm->s_acc = acc0 + stored;
        __syncthreads();
    }

    // ---- zero-fill remaining detection slots ----
    __syncthreads();
    int accF = sm->s_acc;
    for (int a = accF + t; a < DETS; a += TPB) {
        stf(out, b * (DETS * 4) + a * 4 + 0, 0.f, out_size);
        stf(out, b * (DETS * 4) + a * 4 + 1, 0.f, out_size);
        stf(out, b * (DETS * 4) + a * 4 + 2, 0.f, out_size);
        stf(out, b * (DETS * 4) + a * 4 + 3, 0.f, out_size);
        stf(out, Bn * DETS * 4 + b * DETS + a, 0.f, out_size);
        stf(out, Bn * DETS * 5 + b * DETS + a, 0.f, out_size);
        stf(out, Bn * DETS * 6 + b * DETS + a, 0.f, out_size);
    }

    // ---- restore zeros for next graph replay ----
    if (t == 0) g_cnt[b] = 0;
}

// ------------------------------------------------------------------
// launcher
// ------------------------------------------------------------------
extern "C" void kernel_launch(void* const* d_in, const int* in_sizes, int n_in,
                              void* d_out, int out_size) {
    const float* logits = nullptr;
    const float* reg    = nullptr;
    const float* props  = nullptr;
    for (int i = 0; i < n_in; i++) {
        if      (in_sizes[i] == Bn * Nn * Cn)     logits = (const float*)d_in[i];
        else if (in_sizes[i] == Bn * Nn * Cn * 4) reg    = (const float*)d_in[i];
        else if (in_sizes[i] == Bn * Nn * 4)      props  = (const float*)d_in[i];
    }
    if (!logits && n_in > 0) logits = (const float*)d_in[0];
    if (!reg    && n_in > 1) reg    = (const float*)d_in[1];
    if (!props  && n_in > 2) props  = (const float*)d_in[2];

    cudaFuncSetAttribute(k_nms, cudaFuncAttributeMaxDynamicSharedMemorySize,
                         (int)sizeof(SM));

    k_cand<<<(Bn * Nn) / 32, 256>>>(logits, reg, props);
    k_nms<<<Bn, TPB, sizeof(SM)>>>(reg, props, (float*)d_out, out_size);
}

// round 17
// speedup vs baseline: 1.6095x; 1.6095x over previous
#include <cuda_runtime.h>
#include <cstdint>

#define Bn    8
#define Nn    8192
#define Cn    91
#define CAPc  163840          // >= max kept candidates per image
#define NB    9216            // histogram bins over score float bits >> 12
#define BASE_BIN 251084       // bits(0.05f) >> 12
#define SEL_CAP 512
#define TPB   1024
#define DETS  100
#define CLIPV 4.135166556742356f   // log(1000/16)
#define FULLM 0xffffffffu

// ------------------------------------------------------------------
// static device scratch (zero-initialized at load; k_nms restores the
// zeros it consumed -> graph-replay deterministic)
// ------------------------------------------------------------------
__device__ unsigned long long g_keys[Bn][CAPc];
__device__ int                g_cnt [Bn];
__device__ int                g_hist[Bn][NB];

__device__ __forceinline__ void stf(float* o, int i, float v, int n) {
    if (i < n) o[i] = v;
}

// reference-rounding IoU on offset coordinates; returns (iou > 0.5)
__device__ __forceinline__ bool iou_sup(float4 A, float4 Bx, float off) {
    float ax1 = A.x + off, ay1 = A.y + off, ax2 = A.z + off, ay2 = A.w + off;
    float bx1 = Bx.x + off, by1 = Bx.y + off, bx2 = Bx.z + off, by2 = Bx.w + off;
    float ltx = fmaxf(ax1, bx1), lty = fmaxf(ay1, by1);
    float rbx = fminf(ax2, bx2), rby = fminf(ay2, by2);
    float ww = fmaxf(rbx - ltx, 0.f), hh = fmaxf(rby - lty, 0.f);
    float inter = ww * hh;
    float a1 = (ax2 - ax1) * (ay2 - ay1);
    float a2 = (bx2 - bx1) * (by2 - by1);
    float iou = __fdiv_rn(inter, a1 + a2 - inter + 1e-9f);
    return iou > 0.5f;
}

// byte-identical box decode for candidate (g, c)
__device__ __forceinline__ float4 decode_box(const float* __restrict__ reg,
                                             const float* __restrict__ props,
                                             int g, int c) {
    float4 p = reinterpret_cast<const float4*>(props)[g];
    float w  = p.z - p.x;
    float h  = p.w - p.y;
    float cx = p.x + 0.5f * w;
    float cy = p.y + 0.5f * h;
    const float4* Q = reinterpret_cast<const float4*>(reg + (size_t)g * (Cn * 4));
    float4 q = Q[c];
    float dx = __fdiv_rn(q.x, 10.0f);
    float dy = __fdiv_rn(q.y, 10.0f);
    float dw = fminf(__fdiv_rn(q.z, 5.0f), CLIPV);
    float dh = fminf(__fdiv_rn(q.w, 5.0f), CLIPV);
    float pcx = dx * w + cx;
    float pcy = dy * h + cy;
    float pw  = expf(dw) * w;
    float ph  = expf(dh) * h;
    float x1 = fminf(fmaxf(pcx - 0.5f * pw, 0.f), 800.f);
    float y1 = fminf(fmaxf(pcy - 0.5f * ph, 0.f), 800.f);
    float x2 = fminf(fmaxf(pcx + 0.5f * pw, 0.f), 800.f);
    float y2 = fminf(fmaxf(pcy + 0.5f * ph, 0.f), 800.f);
    return make_float4(x1, y1, x2, y2);
}

// decode + filter + key emit for one proposal's survivors (warp-wide)
__device__ __forceinline__ void emit_prop(int g, int lane,
                                          unsigned mA, unsigned mB, unsigned mC,
                                          float e0, float e1, float e2, float s,
                                          const float* __restrict__ reg,
                                          const float* __restrict__ props,
                                          bool& ok, float& sc, int& c) {
    int c0  = __popc(mA);
    int c01 = c0 + __popc(mB);
    int tot = c01 + __popc(mC);
    ok = false; sc = 0.f; c = 0;
    if (tot == 0) return;

    int src = 0, k = 0;
    if (lane < c0)       { k = 0; src = __fns(mA, 0, lane + 1); }
    else if (lane < c01) { k = 1; src = __fns(mB, 0, lane - c0 + 1); }
    else if (lane < tot) { k = 2; src = __fns(mC, 0, lane - c01 + 1); }
    src &= 31;
    float eA = __shfl_sync(FULLM, e0, src);
    float eB = __shfl_sync(FULLM, e1, src);
    float eC = __shfl_sync(FULLM, e2, src);
    float e  = (k == 2) ? eC : ((k == 1) ? eB : eA);
    c = src + (k << 5);

    ok = (lane < tot);
    sc = __fdiv_rn(e, s);                 // exact softmax value
    ok = ok && (sc > 0.05f);
    if (ok) {
        float4 bx = decode_box(reg, props, g, c);
        ok = ((bx.z - bx.x) >= 1.0f) && ((bx.w - bx.y) >= 1.0f);
    }
}

// ------------------------------------------------------------------
// K1: four proposals per warp, interleaved chains + histogram
// ------------------------------------------------------------------
__global__ __launch_bounds__(256) void k_cand(const float* __restrict__ logits,
                                              const float* __restrict__ reg,
                                              const float* __restrict__ props) {
    int warp = threadIdx.x >> 5;
    int lane = threadIdx.x & 31;
    int g0 = blockIdx.x * 32 + warp * 4;      // 4 proposals, same image
    int b  = g0 >> 13;

    float l0[4], l1[4], l2[4], mx[4];
    #pragma unroll
    for (int p = 0; p < 4; p++) {
        const float* L = logits + (size_t)(g0 + p) * Cn;
        l0[p] = L[lane];
        l1[p] = (lane + 32 < Cn) ? L[lane + 32] : -1e30f;
        l2[p] = (lane + 64 < Cn) ? L[lane + 64] : -1e30f;
    }
    #pragma unroll
    for (int p = 0; p < 4; p++) mx[p] = fmaxf(l0[p], fmaxf(l1[p], l2[p]));
    #pragma unroll
    for (int o = 16; o; o >>= 1) {
        #pragma unroll
        for (int p = 0; p < 4; p++)
            mx[p] = fmaxf(mx[p], __shfl_xor_sync(FULLM, mx[p], o));
    }

    float e0[4], e1[4], e2[4], sden[4];
    #pragma unroll
    for (int p = 0; p < 4; p++) {
        e0[p] = expf(l0[p] - mx[p]);
        e1[p] = (lane + 32 < Cn) ? expf(l1[p] - mx[p]) : 0.0f;
        e2[p] = (lane + 64 < Cn) ? expf(l2[p] - mx[p]) : 0.0f;
        sden[p] = e0[p] + e1[p] + e2[p];
    }
    #pragma unroll
    for (int o = 16; o; o >>= 1) {
        #pragma unroll
        for (int p = 0; p < 4; p++)
            sden[p] += __shfl_xor_sync(FULLM, sden[p], o);
    }

    unsigned mA[4], mB[4], mC[4];
    unsigned anym = 0;
    #pragma unroll
    for (int p = 0; p < 4; p++) {
        float pt = 0.0497f * sden[p];   // conservative prefilter (>> 1ulp margin)
        mA[p] = __ballot_sync(FULLM, (lane >= 1) && (e0[p] > pt));
        mB[p] = __ballot_sync(FULLM, e1[p] > pt);
        mC[p] = __ballot_sync(FULLM, e2[p] > pt);
        anym |= mA[p] | mB[p] | mC[p];
    }
    if (anym == 0u) return;                   // warp-uniform

    bool ok[4]; float sc[4]; int cc[4];
    #pragma unroll
    for (int p = 0; p < 4; p++)
        emit_prop(g0 + p, lane, mA[p], mB[p], mC[p],
                  e0[p], e1[p], e2[p], sden[p], reg, props,
                  ok[p], sc[p], cc[p]);

    unsigned fm[4]; int pc[4];
    int tot = 0;
    #pragma unroll
    for (int p = 0; p < 4; p++) {
        fm[p] = __ballot_sync(FULLM, ok[p]);
        pc[p] = __popc(fm[p]);
        tot += pc[p];
    }
    if (tot) {
        int base = 0;
        if (lane == 0) base = atomicAdd(&g_cnt[b], tot);
        base = __shfl_sync(FULLM, base, 0);
        unsigned below = (1u << lane) - 1u;
        int off = base;
        #pragma unroll
        for (int p = 0; p < 4; p++) {
            if (ok[p]) {
                int pos = off + __popc(fm[p] & below);
                if (pos < CAPc) {
                    int n = (g0 + p) & (Nn - 1);
                    unsigned m = (unsigned)(n * 90 + (cc[p] - 1));
                    unsigned sbb = __float_as_uint(sc[p]);
                    g_keys[b][pos] = ((unsigned long long)sbb << 32) | (0xFFFFFFFFu - m);
                    int bin = (int)(sbb >> 12) - BASE_BIN;
                    bin = max(0, min(bin, NB - 1));
                    atomicAdd(&g_hist[b][bin], 1);
                }
            }
        }
        (void)off;
        #pragma unroll
        for (int p = 0; p < 4; p++) { }
        // recompute offsets properly (off must advance per p)
    }
}

// NOTE: the loop above must advance `off` per proposal; re-issue corrected
// kernel below is the one actually launched.
__global__ __launch_bounds__(256) void k_cand_fix(const float* __restrict__ logits,
                                                  const float* __restrict__ reg,
                                                  const float* __restrict__ props) {
    int warp = threadIdx.x >> 5;
    int lane = threadIdx.x & 31;
    int g0 = blockIdx.x * 32 + warp * 4;
    int b  = g0 >> 13;

    float l0[4], l1[4], l2[4], mx[4];
    #pragma unroll
    for (int p = 0; p < 4; p++) {
        const float* L = logits + (size_t)(g0 + p) * Cn;
        l0[p] = L[lane];
        l1[p] = (lane + 32 < Cn) ? L[lane + 32] : -1e30f;
        l2[p] = (lane + 64 < Cn) ? L[lane + 64] : -1e30f;
    }
    #pragma unroll
    for (int p = 0; p < 4; p++) mx[p] = fmaxf(l0[p], fmaxf(l1[p], l2[p]));
    #pragma unroll
    for (int o = 16; o; o >>= 1) {
        #pragma unroll
        for (int p = 0; p < 4; p++)
            mx[p] = fmaxf(mx[p], __shfl_xor_sync(FULLM, mx[p], o));
    }

    float e0[4], e1[4], e2[4], sden[4];
    #pragma unroll
    for (int p = 0; p < 4; p++) {
        e0[p] = expf(l0[p] - mx[p]);
        e1[p] = (lane + 32 < Cn) ? expf(l1[p] - mx[p]) : 0.0f;
        e2[p] = (lane + 64 < Cn) ? expf(l2[p] - mx[p]) : 0.0f;
        sden[p] = e0[p] + e1[p] + e2[p];
    }
    #pragma unroll
    for (int o = 16; o; o >>= 1) {
        #pragma unroll
        for (int p = 0; p < 4; p++)
            sden[p] += __shfl_xor_sync(FULLM, sden[p], o);
    }

    unsigned mA[4], mB[4], mC[4];
    unsigned anym = 0;
    #pragma unroll
    for (int p = 0; p < 4; p++) {
        float pt = 0.0497f * sden[p];
        mA[p] = __ballot_sync(FULLM, (lane >= 1) && (e0[p] > pt));
        mB[p] = __ballot_sync(FULLM, e1[p] > pt);
        mC[p] = __ballot_sync(FULLM, e2[p] > pt);
        anym |= mA[p] | mB[p] | mC[p];
    }
    if (anym == 0u) return;

    bool ok[4]; float sc[4]; int cc[4];
    #pragma unroll
    for (int p = 0; p < 4; p++)
        emit_prop(g0 + p, lane, mA[p], mB[p], mC[p],
                  e0[p], e1[p], e2[p], sden[p], reg, props,
                  ok[p], sc[p], cc[p]);

    unsigned fm[4]; int pc[4];
    int tot = 0;
    #pragma unroll
    for (int p = 0; p < 4; p++) {
        fm[p] = __ballot_sync(FULLM, ok[p]);
        pc[p] = __popc(fm[p]);
        tot += pc[p];
    }
    if (tot) {
        int base = 0;
        if (lane == 0) base = atomicAdd(&g_cnt[b], tot);
        base = __shfl_sync(FULLM, base, 0);
        unsigned below = (1u << lane) - 1u;
        int off = base;
        #pragma unroll
        for (int p = 0; p < 4; p++) {
            if (ok[p]) {
                int pos = off + __popc(fm[p] & below);
                if (pos < CAPc) {
                    int n = (g0 + p) & (Nn - 1);
                    unsigned m = (unsigned)(n * 90 + (cc[p] - 1));
                    unsigned sbb = __float_as_uint(sc[p]);
                    g_keys[b][pos] = ((unsigned long long)sbb << 32) | (0xFFFFFFFFu - m);
                    int bin = (int)(sbb >> 12) - BASE_BIN;
                    bin = max(0, min(bin, NB - 1));
                    atomicAdd(&g_hist[b][bin], 1);
                }
            }
            off += pc[p];
        }
    }
}

// ------------------------------------------------------------------
// K2 shared memory (window = 512)
// ------------------------------------------------------------------
struct SM {
    float4 sbox[SEL_CAP];               // window boxes (sorted order)
    float4 cls_acc[32][DETS];           // fallback-path accepted scratch
    float4 abox[DETS];                  // global accepted boxes
    unsigned long long skey[SEL_CAP];
    unsigned long long skey2[SEL_CAP];  // double buffer for bitonic stages
    unsigned mask[SEL_CAP][4];          // per-rank suppression bitmask (<=128)
    int    slbl[SEL_CAP];
    int    sfx[NB];
    int    chunkcnt[32][128];           // per-(chunk,warp) class counts / bases
    int    cls_rank[SEL_CAP];
    int    cls_list[SEL_CAP];
    int    sflag[SEL_CAP];
    int    presup[SEL_CAP];
    int    cls_cnt[128];
    int    cls_off[96];
    int    albl[DETS];
    int    wtot[32], wexc[32], wsum[32];
    int    s_cnt, s_acc, s_surv;
};

__global__ __launch_bounds__(TPB) void k_nms(const float* __restrict__ reg,
                                             const float* __restrict__ props,
                                             float* __restrict__ out, int out_size) {
    extern __shared__ __align__(16) char smraw[];
    SM* sm = reinterpret_cast<SM*>(smraw);
    int b = blockIdx.x;
    int t = threadIdx.x;
    int lane = t & 31;
    int warp = t >> 5;

    int Ktot = min(g_cnt[b], CAPc);

    // ---- load histogram (built by k_cand) + restore zeros ----
    const int PER = NB / TPB;   // 9
    int lo = t * PER;
    int cnts[PER];
    #pragma unroll
    for (int i = 0; i < PER; i++) {
        cnts[i] = g_hist[b][lo + i];
        g_hist[b][lo + i] = 0;
    }

    // ---- hierarchical suffix sums ----
    int ls = 0;
    #pragma unroll
    for (int i = 0; i < PER; i++) ls += cnts[i];
    int v = ls;
    #pragma unroll
    for (int off = 1; off < 32; off <<= 1) {
        int u = __shfl_down_sync(FULLM, v, off);
        if (lane + off < 32) v += u;
    }
    if (lane == 0) sm->wtot[warp] = v;
    __syncthreads();
    if (t < 32) {
        int x = sm->wtot[t];
        int vv = x;
        #pragma unroll
        for (int off = 1; off < 32; off <<= 1) {
            int u = __shfl_down_sync(FULLM, vv, off);
            if (t + off < 32) vv += u;
        }
        sm->wexc[t] = vv - x;
    }
    if (t == 0) sm->s_acc = 0;
    __syncthreads();
    int run = sm->wexc[warp] + (v - ls);
    for (int i = PER - 1; i >= 0; i--) {
        run += cnts[i];
        sm->sfx[lo + i] = run;
    }
    __syncthreads();

    int b_hi = NB;

    while (sm->s_acc < DETS) {
        int top = (b_hi < NB) ? sm->sfx[b_hi] : 0;
        if (b_hi == 0 || sm->sfx[0] - top == 0) break;

        // smallest wlo with sfx[wlo] - top <= SEL_CAP
        int sl = 0, sh = b_hi;
        while (sl < sh) {
            int mid = (sl + sh) >> 1;
            if (sm->sfx[mid] - top <= SEL_CAP) sh = mid; else sl = mid + 1;
        }
        int wlo = sl;
        if (wlo >= b_hi) wlo = b_hi - 1;
        int whi = b_hi;
        b_hi = wlo;

        if (t == 0) sm->s_cnt = 0;
        __syncthreads();
        // ---- MLP-8 selection scan ----
        for (int i0 = 0; i0 < Ktot; i0 += TPB * 8) {
            unsigned long long kv[8];
            #pragma unroll
            for (int k = 0; k < 8; k++) {
                int i = i0 + k * TPB + t;
                kv[k] = (i < Ktot) ? g_keys[b][i] : 0ULL;
            }
            #pragma unroll
            for (int k = 0; k < 8; k++) {
                if (kv[k]) {
                    int bin = (int)((unsigned)(kv[k] >> 32) >> 12) - BASE_BIN;
                    bin = max(0, min(bin, NB - 1));
                    if (bin >= wlo && bin < whi) {
                        int pos = atomicAdd(&sm->s_cnt, 1);
                        if (pos < SEL_CAP) sm->skey[pos] = kv[k];
                    }
                }
            }
        }
        __syncthreads();
        int nsel = min(sm->s_cnt, SEL_CAP);
        if (nsel == 0) continue;

        if (t >= nsel && t < SEL_CAP) sm->skey[t] = 0ULL;
        __syncthreads();

        // ---- bitonic sort, descending, P=512 (warps 0-15 active) ----
        {
            unsigned long long key = (t < SEL_CAP) ? sm->skey[t] : 0ULL;
            int useB = 1;
            #pragma unroll
            for (int k2 = 2; k2 <= SEL_CAP; k2 <<= 1) {
                for (int j = k2 >> 1; j > 0; j >>= 1) {
                    if (j >= 32) {
                        unsigned long long* W = useB ? sm->skey2 : sm->skey;
                        if (t < SEL_CAP) W[t] = key;
                        __syncthreads();
                        if (t < SEL_CAP) {
                            unsigned long long partner = W[t ^ j];
                            bool desc    = ((t & k2) == 0);
                            bool lowerIx = ((t & j) == 0);
                            if ((desc == lowerIx) == (partner > key)) key = partner;
                        }
                        useB ^= 1;
                    } else if (t < SEL_CAP) {
                        unsigned long long partner = __shfl_xor_sync(FULLM, key, j);
                        bool desc    = ((t & k2) == 0);
                        bool lowerIx = ((t & j) == 0);
                        if ((desc == lowerIx) == (partner > key)) key = partner;
                    }
                }
            }
            __syncthreads();
            if (t < SEL_CAP) sm->skey[t] = key;
            __syncthreads();
        }

        // ---- decode boxes + labels in sorted order; reset counters ----
        int mylbl;
        if (t < nsel) {
            unsigned m = 0xFFFFFFFFu - (unsigned)sm->skey[t];
            int n = (int)(m / 90u);
            int c = (int)(m % 90u) + 1;
            sm->sbox[t] = decode_box(reg, props, b * Nn + n, c);
            sm->slbl[t] = c;
            mylbl = c;
        } else {
            mylbl = 96 + lane;            // unique-per-lane pad label
        }
        if (t < SEL_CAP) sm->sflag[t] = 0;
        {
            #pragma unroll
            for (int i = 0; i < 4; i++) sm->chunkcnt[(t * 4 + i) >> 7][(t * 4 + i) & 127] = 0;
        }
        __syncthreads();

        // ---- parallel per-chunk ranks: warp w handles items w*32+lane ----
        unsigned peers = __match_any_sync(FULLM, mylbl);
        int lrank = __popc(peers & ((1u << lane) - 1u));
        int leader = __ffs(peers) - 1;
        if (lane == leader) sm->chunkcnt[warp][mylbl] = __popc(peers);
        __syncthreads();

        // ---- per-class prefix across the 32 chunks (128 threads) ----
        if (t < 128) {
            int run2 = 0;
            #pragma unroll 1
            for (int w = 0; w < 32; w++) {
                int tmp = sm->chunkcnt[w][t];
                sm->chunkcnt[w][t] = run2;   // becomes chunk base
                run2 += tmp;
            }
            sm->cls_cnt[t] = run2;
        }
        __syncthreads();

        if (t < nsel) sm->cls_rank[t] = sm->chunkcnt[warp][mylbl] + lrank;
        __syncthreads();

        // ---- exclusive offsets over classes 0..95 ----
        if (t < 32) {
            int c0i = t * 3;
            int s0 = sm->cls_cnt[c0i], s1 = sm->cls_cnt[c0i + 1], s2 = sm->cls_cnt[c0i + 2];
            int tt = s0 + s1 + s2;
            int rn = tt;
            #pragma unroll
            for (int off = 1; off < 32; off <<= 1) {
                int u = __shfl_up_sync(FULLM, rn, off);
                if (lane >= off) rn += u;
            }
            int ex = rn - tt;
            sm->cls_off[c0i] = ex;
            sm->cls_off[c0i + 1] = ex + s0;
            sm->cls_off[c0i + 2] = ex + s0 + s1;
        }
        __syncthreads();

        // ---- scatter per-class lists (stable: score order within class) --
        if (t < nsel) sm->cls_list[sm->cls_off[mylbl] + sm->cls_rank[t]] = t;
        int acc0 = sm->s_acc;
        int quota = DETS - acc0;
        __syncthreads();

        // ---- phase A: presuppression by prior-round accepted boxes ----
        {
            int ps = 0;
            if (t < nsel && acc0 > 0) {
                float4 bi = sm->sbox[t];
                int li = mylbl;
                float offv = (float)li * 801.0f;
                for (int a = 0; a < acc0; a++) {
                    if (sm->albl[a] == li && iou_sup(sm->abox[a], bi, offv)) { ps = 1; break; }
                }
            }
            if (t < SEL_CAP) sm->presup[t] = ps;
        }

        // ---- phase B: parallel mask build (classes with cnt <= 128) ----
        if (t < nsel) {
            int c = mylbl;
            int cnt = sm->cls_cnt[c];
            if (cnt <= 128) {
                int off = sm->cls_off[c];
                int r = sm->cls_rank[t];
                float4 bi = sm->sbox[t];
                float offv = (float)c * 801.0f;
                unsigned w0 = 0, w1 = 0, w2 = 0, w3 = 0;
                for (int j = r + 1; j < cnt; j++) {
                    int widx = sm->cls_list[off + j];
                    if (iou_sup(bi, sm->sbox[widx], offv)) {
                        int wsel = j >> 5;
                        unsigned bit = 1u << (j & 31);
                        if      (wsel == 0) w0 |= bit;
                        else if (wsel == 1) w1 |= bit;
                        else if (wsel == 2) w2 |= bit;
                        else                w3 |= bit;
                    }
                }
                sm->mask[off + r][0] = w0;
                sm->mask[off + r][1] = w1;
                sm->mask[off + r][2] = w2;
                sm->mask[off + r][3] = w3;
            }
        }
        __syncthreads();

        // ---- phase C: 90 concurrent single-lane greedy word-walks ----
        if (t < 90) {
            int c = t + 1;
            int cnt = sm->cls_cnt[c];
            if (cnt > 0 && cnt <= 128) {
                int off = sm->cls_off[c];
                unsigned S0 = 0, S1 = 0, S2 = 0, S3 = 0;
                int newacc = 0;
                for (int j = 0; j < cnt; j++) {
                    int wsel = j >> 5;
                    unsigned bit = 1u << (j & 31);
                    unsigned Sw = (wsel == 0) ? S0 : (wsel == 1) ? S1 : (wsel == 2) ? S2 : S3;
                    int widx = sm->cls_list[off + j];
                    if (!(Sw & bit) && !sm->presup[widx]) {
                        sm->sflag[widx] = 1;
                        newacc++;
                        if (newacc >= quota) break;
                        S0 |= sm->mask[off + j][0];
                        S1 |= sm->mask[off + j][1];
                        S2 |= sm->mask[off + j][2];
                        S3 |= sm->mask[off + j][3];
                    }
                }
            }
        }

        // ---- fallback: classes with cnt > 128 use serial warp greedy ----
        #pragma unroll
        for (int jc = 0; jc < 3; jc++) {
            int c = warp + 1 + 32 * jc;
            if (c > 90) continue;
            int cnt = sm->cls_cnt[c];
            if (cnt <= 128) continue;       // handled by mask path
            int off = sm->cls_off[c];
            float offv = (float)c * 801.0f;

            int nacc = 0;
            for (int a0 = 0; a0 < acc0; a0 += 32) {
                int a = a0 + lane;
                bool mth = (a < acc0) && (sm->albl[a] == c);
                unsigned mm = __ballot_sync(FULLM, mth);
                if (mth) sm->cls_acc[warp][nacc + __popc(mm & ((1u << lane) - 1u))] = sm->abox[a];
                nacc += __popc(mm);
            }

            int newacc = 0;
            for (int j = 0; j < cnt; j++) {
                int i = sm->cls_list[off + j];
                float4 bx = sm->sbox[i];
                bool sup = false;
                for (int a = lane; a < nacc; a += 32)
                    sup |= iou_sup(sm->cls_acc[warp][a], bx, offv);
                if (!__any_sync(FULLM, sup)) {
                    if (lane == 0) {
                        sm->sflag[i] = 1;
                        sm->cls_acc[warp][nacc] = bx;
                    }
                    nacc++;
                    newacc++;
                    if (newacc >= quota) break;
                }
            }
        }
        __syncthreads();

        // ---- prefix over survivor flags; output first quota in order ----
        {
            int f = (t < SEL_CAP) ? sm->sflag[t] : 0;
            int scn = f;
            #pragma unroll
            for (int off = 1; off < 32; off <<= 1) {
                int u = __shfl_up_sync(FULLM, scn, off);
                if (lane >= off) scn += u;
            }
            if (lane == 31) sm->wsum[warp] = scn;
            __syncthreads();
            if (t < 32) {
                int x = sm->wsum[t];
                int s2 = x;
                #pragma unroll
                for (int off = 1; off < 32; off <<= 1) {
                    int u = __shfl_up_sync(FULLM, s2, off);
                    if (t >= off) s2 += u;
                }
                sm->wsum[t] = s2 - x;
            }
            __syncthreads();
            int incl = scn + sm->wsum[warp];
            int r = incl - f;
            if (f && (acc0 + r) < DETS) {
                int slot = acc0 + r;
                float4 bx = sm->sbox[t];
                int lbl = sm->slbl[t];
                sm->abox[slot] = bx;
                sm->albl[slot] = lbl;
                float sc = __uint_as_float((unsigned)(sm->skey[t] >> 32));
                stf(out, b * (DETS * 4) + slot * 4 + 0, bx.x, out_size);
                stf(out, b * (DETS * 4) + slot * 4 + 1, bx.y, out_size);
                stf(out, b * (DETS * 4) + slot * 4 + 2, bx.z, out_size);
                stf(out, b * (DETS * 4) + slot * 4 + 3, bx.w, out_size);
                stf(out, Bn * DETS * 4 + b * DETS + slot, sc, out_size);
                stf(out, Bn * DETS * 5 + b * DETS + slot, (float)lbl, out_size);
                stf(out, Bn * DETS * 6 + b * DETS + slot, 1.0f, out_size);
            }
            if (t == TPB - 1) sm->s_surv = incl;
            __syncthreads();
            if (t == 0) sm->s_acc = min(acc0 + sm->s_surv, DETS);
            __syncthreads();
        }
    }

    // ---- zero-fill remaining detection slots ----
    __syncthreads();
    int accF = sm->s_acc;
    for (int a = accF + t; a < DETS; a += TPB) {
        stf(out, b * (DETS * 4) + a * 4 + 0, 0.f, out_size);
        stf(out, b * (DETS * 4) + a * 4 + 1, 0.f, out_size);
        stf(out, b * (DETS * 4) + a * 4 + 2, 0.f, out_size);
        stf(out, b * (DETS * 4) + a * 4 + 3, 0.f, out_size);
        stf(out, Bn * DETS * 4 + b * DETS + a, 0.f, out_size);
        stf(out, Bn * DETS * 5 + b * DETS + a, 0.f, out_size);
        stf(out, Bn * DETS * 6 + b * DETS + a, 0.f, out_size);
    }

    // ---- restore zeros for next graph replay ----
    if (t == 0) g_cnt[b] = 0;
}

// ------------------------------------------------------------------
// launcher
// ------------------------------------------------------------------
extern "C" void kernel_launch(void* const* d_in, const int* in_sizes, int n_in,
                              void* d_out, int out_size) {
    const float* logits = nullptr;
    const float* reg    = nullptr;
    const float* props  = nullptr;
    for (int i = 0; i < n_in; i++) {
        if      (in_sizes[i] == Bn * Nn * Cn)     logits = (const float*)d_in[i];
        else if (in_sizes[i] == Bn * Nn * Cn * 4) reg    = (const float*)d_in[i];
        else if (in_sizes[i] == Bn * Nn * 4)      props  = (const float*)d_in[i];
    }
    if (!logits && n_in > 0) logits = (const float*)d_in[0];
    if (!reg    && n_in > 1) reg    = (const float*)d_in[1];
    if (!props  && n_in > 2) props  = (const float*)d_in[2];

    cudaFuncSetAttribute(k_nms, cudaFuncAttributeMaxDynamicSharedMemorySize,
                         (int)sizeof(SM));

    k_cand_fix<<<(Bn * Nn) / 32, 256>>>(logits, reg, props);
    k_nms<<<Bn, TPB, sizeof(SM)>>>(reg, props, (float*)d_out, out_size);
}